// round 15
// baseline (speedup 1.0000x reference)
#include <cuda_runtime.h>
#include <cuda_fp16.h>
#include <cstdint>
#include <math.h>

#define S_LEN 2048
#define HID_DIM 4096
#define NH 32
#define NKV 8
#define DH 128
#define KVW (NKV * DH)     // 1024
#define QKVW 6144          // fused Q(4096) + K(1024) + V(1024) width

// ---------------------------------------------------------------------------
// Scratch (device globals: allocation-free)
// ---------------------------------------------------------------------------
__device__ __half g_hid_hi[S_LEN * HID_DIM];
__device__ __half g_hid_lo[S_LEN * HID_DIM];
__device__ __half g_qkv_hi[S_LEN * QKVW];
__device__ __half g_qkv_lo[S_LEN * QKVW];
__device__ __half g_at_hi[S_LEN * HID_DIM];
__device__ __half g_at_lo[S_LEN * HID_DIM];
__device__ __half g_wqkvT[QKVW * HID_DIM];
__device__ __half g_woT[HID_DIM * HID_DIM];

// ---------------------------------------------------------------------------
// PTX helpers (baseline sm_80 PTX — safe on compute_103)
// ---------------------------------------------------------------------------
__device__ __forceinline__ uint32_t smem_u32(const void* p) {
    return (uint32_t)__cvta_generic_to_shared(p);
}
#define CP_ASYNC16(sa, gp) \
    asm volatile("cp.async.cg.shared.global [%0], [%1], 16;" :: "r"(sa), "l"(gp))
#define CP_COMMIT() asm volatile("cp.async.commit_group;" ::: "memory")
#define CP_WAIT(n)  asm volatile("cp.async.wait_group %0;" :: "n"(n) : "memory")

#define LDSM_X4(r0, r1, r2, r3, a) \
    asm volatile("ldmatrix.sync.aligned.m8n8.x4.shared.b16 {%0,%1,%2,%3},[%4];" \
        : "=r"(r0), "=r"(r1), "=r"(r2), "=r"(r3) : "r"(a))
#define LDSM_X4T(r0, r1, r2, r3, a) \
    asm volatile("ldmatrix.sync.aligned.m8n8.x4.trans.shared.b16 {%0,%1,%2,%3},[%4];" \
        : "=r"(r0), "=r"(r1), "=r"(r2), "=r"(r3) : "r"(a))
#define MMA16816(d, a0, a1, a2, a3, b0, b1) \
    asm volatile("mma.sync.aligned.m16n8k16.row.col.f32.f16.f16.f32 " \
        "{%0,%1,%2,%3},{%4,%5,%6,%7},{%8,%9},{%0,%1,%2,%3};" \
        : "+f"((d)[0]), "+f"((d)[1]), "+f"((d)[2]), "+f"((d)[3]) \
        : "r"(a0), "r"(a1), "r"(a2), "r"(a3), "r"(b0), "r"(b1))

__device__ __forceinline__ uint32_t pack_h2(__half a, __half b) {
    __half2 h = __halves2half2(a, b);
    return *(uint32_t*)&h;
}

// ---------------------------------------------------------------------------
// Split fp32 -> (hi, lo) fp16, elementwise
// ---------------------------------------------------------------------------
__global__ void conv_hilo_kernel(const float* __restrict__ x,
                                 __half* __restrict__ hi,
                                 __half* __restrict__ lo, int n)
{
    int i = (blockIdx.x * blockDim.x + threadIdx.x) * 4;
    if (i >= n) return;
    float4 v = *(const float4*)(x + i);
    __half h0 = __float2half_rn(v.x);
    __half h1 = __float2half_rn(v.y);
    __half h2 = __float2half_rn(v.z);
    __half h3 = __float2half_rn(v.w);
    __half l0 = __float2half_rn(v.x - __half2float(h0));
    __half l1 = __float2half_rn(v.y - __half2float(h1));
    __half l2 = __float2half_rn(v.z - __half2float(h2));
    __half l3 = __float2half_rn(v.w - __half2float(h3));
    __half2* hp = (__half2*)(hi + i);
    __half2* lp = (__half2*)(lo + i);
    hp[0] = __half2(h0, h1); hp[1] = __half2(h2, h3);
    lp[0] = __half2(l0, l1); lp[1] = __half2(l2, l3);
}

// ---------------------------------------------------------------------------
// Transpose + round all 4 weights in one launch (grid.z selects weight).
// ---------------------------------------------------------------------------
__global__ void conv_t_all_kernel(const float* __restrict__ wq,
                                  const float* __restrict__ wk,
                                  const float* __restrict__ wv,
                                  const float* __restrict__ wo,
                                  __half* __restrict__ wqkv,
                                  __half* __restrict__ wot)
{
    const int z = blockIdx.z;
    const float* B;
    __half* T;
    int N;
    if (z == 0)      { B = wq; T = wqkv;                                  N = HID_DIM; }
    else if (z == 1) { B = wk; T = wqkv + (size_t)HID_DIM * HID_DIM;      N = KVW; }
    else if (z == 2) { B = wv; T = wqkv + (size_t)(HID_DIM + KVW) * HID_DIM; N = KVW; }
    else             { B = wo; T = wot;                                   N = HID_DIM; }

    const int n0 = blockIdx.x * 32;
    if (n0 >= N) return;
    const int k0 = blockIdx.y * 32;

    __shared__ float t[32][33];
    const int tx = threadIdx.x, ty = threadIdx.y;
#pragma unroll
    for (int i = 0; i < 32; i += 8)
        t[ty + i][tx] = B[(size_t)(k0 + ty + i) * N + n0 + tx];
    __syncthreads();
#pragma unroll
    for (int i = 0; i < 32; i += 8) {
        size_t o = (size_t)(n0 + ty + i) * HID_DIM + k0 + tx;
        T[o] = __float2half_rn(t[tx][ty + i]);
    }
}

// ---------------------------------------------------------------------------
// fp16 split-A GEMM: D = Ah*B + Al*B.  B transposed [N,K] fp16.
// CTA tile 128x256 (BN=256 halves A re-read traffic), 512 threads / 16 warps
// (warp tile 32x64), k64 chunks, 2-stage cp.async (issue after sync).
// ---------------------------------------------------------------------------
#define TLD 72
#define SMAT_A (128 * TLD * 2)                // 18432
#define SMAT_B (256 * TLD * 2)                // 36864
#define STG_BYTES (2 * SMAT_A + SMAT_B)       // 73728 (Ah, Al, B)
#define GEMM_SMEM (2 * STG_BYTES)             // 147456

__global__ void __launch_bounds__(512, 1) gemm_fp16x2_kernel(
    const __half* __restrict__ Ahi, const __half* __restrict__ Alo,
    const __half* __restrict__ Bh,
    float* __restrict__ Cf,
    __half* __restrict__ Chi, __half* __restrict__ Clo,
    int M, int N, int K)
{
    extern __shared__ char smem[];
    const uint32_t sb = smem_u32(smem);
    const int tid = threadIdx.x;
    const int lane = tid & 31, wid = tid >> 5;
    const int wm = wid & 3, wn = wid >> 2;     // 4 m-slices x 4 n-slices
    const int m0 = blockIdx.y * 128, n0 = blockIdx.x * 256;

    auto issue = [&](int it) {
        const uint32_t st = sb + (it & 1) * STG_BYTES;
        const int k0 = it * 64;
        // A hi/lo: 128x64, 2 cps/thread each
#pragma unroll
        for (int i = 0; i < 2; i++) {
            int c = tid + i * 512;             // 0..1023
            int row = c >> 3, seg = c & 7;
            uint32_t so = (uint32_t)((row * TLD + seg * 8) * 2);
            size_t gA = (size_t)(m0 + row) * K + k0 + seg * 8;
            CP_ASYNC16(st + so, (const void*)(Ahi + gA));
            CP_ASYNC16(st + SMAT_A + so, (const void*)(Alo + gA));
        }
        // B: 256x64, 4 cps/thread
#pragma unroll
        for (int i = 0; i < 4; i++) {
            int c = tid + i * 512;             // 0..2047
            int row = c >> 3, seg = c & 7;
            uint32_t so = (uint32_t)((row * TLD + seg * 8) * 2);
            size_t gB = (size_t)(n0 + row) * K + k0 + seg * 8;
            CP_ASYNC16(st + 2 * SMAT_A + so, (const void*)(Bh + gB));
        }
        CP_COMMIT();
    };

    float acc[2][8][4];
#pragma unroll
    for (int mi = 0; mi < 2; mi++)
#pragma unroll
        for (int nj = 0; nj < 8; nj++)
#pragma unroll
            for (int r = 0; r < 4; r++) acc[mi][nj][r] = 0.f;

    const int nIter = K >> 6;
    issue(0);

    for (int it = 0; it < nIter; ++it) {
        CP_WAIT(0);
        __syncthreads();
        if (it + 1 < nIter) issue(it + 1);   // after sync: other stage is free

        const uint32_t st = sb + (it & 1) * STG_BYTES;
        const uint32_t ah_b = st;
        const uint32_t al_b = st + SMAT_A;
        const uint32_t bh_b = st + 2 * SMAT_A;

#pragma unroll
        for (int ks = 0; ks < 4; ks++) {
            uint32_t ah[2][4], al[2][4];
            const int arow = wm * 32 + (lane & 15);
            const int acol = ks * 16 + (lane >> 4) * 8;
#pragma unroll
            for (int mi = 0; mi < 2; mi++) {
                uint32_t off = (uint32_t)(((arow + mi * 16) * TLD + acol) * 2);
                LDSM_X4(ah[mi][0], ah[mi][1], ah[mi][2], ah[mi][3], ah_b + off);
                LDSM_X4(al[mi][0], al[mi][1], al[mi][2], al[mi][3], al_b + off);
            }
            const int brow = wn * 64 + (lane & 7) + ((lane >> 4) << 3);
            const int bcol = ks * 16 + (((lane >> 3) & 1) << 3);
#pragma unroll
            for (int nt = 0; nt < 4; nt++) {
                uint32_t off = (uint32_t)(((brow + nt * 16) * TLD + bcol) * 2);
                uint32_t bh[4];
                LDSM_X4(bh[0], bh[1], bh[2], bh[3], bh_b + off);
#pragma unroll
                for (int mi = 0; mi < 2; mi++) {
                    MMA16816(acc[mi][2 * nt], ah[mi][0], ah[mi][1], ah[mi][2], ah[mi][3], bh[0], bh[1]);
                    MMA16816(acc[mi][2 * nt], al[mi][0], al[mi][1], al[mi][2], al[mi][3], bh[0], bh[1]);
                    MMA16816(acc[mi][2 * nt + 1], ah[mi][0], ah[mi][1], ah[mi][2], ah[mi][3], bh[2], bh[3]);
                    MMA16816(acc[mi][2 * nt + 1], al[mi][0], al[mi][1], al[mi][2], al[mi][3], bh[2], bh[3]);
                }
            }
        }
    }

    const int er = lane >> 2, ec = (lane & 3) * 2;
#pragma unroll
    for (int mi = 0; mi < 2; mi++) {
        const int gr = m0 + wm * 32 + mi * 16 + er;
#pragma unroll
        for (int nj = 0; nj < 8; nj++) {
            const int gc = n0 + wn * 64 + nj * 8 + ec;
            if (Chi) {
#pragma unroll
                for (int half_ = 0; half_ < 2; half_++) {
                    float f0 = acc[mi][nj][half_ * 2 + 0];
                    float f1 = acc[mi][nj][half_ * 2 + 1];
                    __half h0 = __float2half_rn(f0);
                    __half h1 = __float2half_rn(f1);
                    __half l0 = __float2half_rn(f0 - __half2float(h0));
                    __half l1 = __float2half_rn(f1 - __half2float(h1));
                    size_t o = (size_t)(gr + half_ * 8) * N + gc;
                    *(__half2*)(Chi + o) = __half2(h0, h1);
                    *(__half2*)(Clo + o) = __half2(l0, l1);
                }
            } else {
                *(float2*)(Cf + (size_t)gr * N + gc) =
                    make_float2(acc[mi][nj][0], acc[mi][nj][1]);
                *(float2*)(Cf + (size_t)(gr + 8) * N + gc) =
                    make_float2(acc[mi][nj][2], acc[mi][nj][3]);
            }
        }
    }
}

// ---------------------------------------------------------------------------
// FA2 attention (unchanged from R13): 8 warps x 16 rows, K 3-term, PV 2-term,
// Q frags hoisted, 3-stage KV pipeline.
// ---------------------------------------------------------------------------
#define LDQ 136
#define AQH 0
#define AQL 34816
#define AKV 69632
#define AMAT 17408
#define AKV_STG (3 * AMAT)            // 52224 (Kh, Kl, Vh)
#define ATT_SMEM (AKV + 3 * AKV_STG)  // 226304

__global__ void __launch_bounds__(256, 1) attn_mma_kernel(
    const __half* __restrict__ QKVh, const __half* __restrict__ QKVl,
    __half* __restrict__ Oh, __half* __restrict__ Ol)
{
    extern __shared__ char sm[];
    const uint32_t sb = smem_u32(sm);
    const int tid = threadIdx.x;
    const int wid = tid >> 5, lane = tid & 31;
    const int qt = 15 - (int)blockIdx.x;     // heavy tiles first
    const int h = blockIdx.y;
    const int kvh = h >> 2;
    const int m0 = qt * 128;
    const int wrow = wid * 16;
    const float scale = 0.08838834764831845f;

    const int koff = HID_DIM + kvh * DH;
    const int voff = HID_DIM + KVW + kvh * DH;

    auto kv_issue = [&](int jt) {
        const uint32_t st = sb + AKV + (jt % 3) * AKV_STG;
#pragma unroll
        for (int i = 0; i < 4; i++) {
            int idx = tid + i * 256;
            int row = idx >> 4, seg = idx & 15;
            uint32_t so = (uint32_t)((row * LDQ + seg * 8) * 2);
            size_t gK = (size_t)(jt * 64 + row) * QKVW + koff + seg * 8;
            size_t gV = (size_t)(jt * 64 + row) * QKVW + voff + seg * 8;
            CP_ASYNC16(st + 0 * AMAT + so, (const void*)(QKVh + gK));
            CP_ASYNC16(st + 1 * AMAT + so, (const void*)(QKVl + gK));
            CP_ASYNC16(st + 2 * AMAT + so, (const void*)(QKVh + gV));
        }
        CP_COMMIT();
    };

    const int nIter = 2 * qt + 2;
    kv_issue(0);

    {
        __half* qh_s = (__half*)(sm + AQH);
        __half* ql_s = (__half*)(sm + AQL);
#pragma unroll
        for (int i = 0; i < 8; i++) {
            int idx = tid + i * 256;
            int row = idx >> 4, seg = idx & 15;
            size_t g = (size_t)(m0 + row) * QKVW + h * DH + seg * 8;
            *(uint4*)(qh_s + row * LDQ + seg * 8) = *(const uint4*)(QKVh + g);
            *(uint4*)(ql_s + row * LDQ + seg * 8) = *(const uint4*)(QKVl + g);
        }
    }
    if (nIter > 1) kv_issue(1);
    __syncthreads();

    const int lrow = lane & 15, lcolh = (lane >> 4) * 8;
    uint32_t qfh[8][4], qfl[8][4];
#pragma unroll
    for (int ks = 0; ks < 8; ks++) {
        uint32_t aoff = (uint32_t)(((wrow + lrow) * LDQ + ks * 16 + lcolh) * 2);
        LDSM_X4(qfh[ks][0], qfh[ks][1], qfh[ks][2], qfh[ks][3], sb + AQH + aoff);
        LDSM_X4(qfl[ks][0], qfl[ks][1], qfl[ks][2], qfl[ks][3], sb + AQL + aoff);
    }

    float o[16][4];
#pragma unroll
    for (int nf = 0; nf < 16; nf++)
#pragma unroll
        for (int r = 0; r < 4; r++) o[nf][r] = 0.f;
    float rM0 = -1e30f, rM1 = -1e30f, rL0 = 0.f, rL1 = 0.f;

    const int r0l = lane >> 2, c0l = (lane & 3) * 2;
    const int gq0 = m0 + wrow + r0l, gq1 = gq0 + 8;

    for (int jt = 0; jt < nIter; jt++) {
        if (jt + 1 < nIter) { CP_WAIT(1); } else { CP_WAIT(0); }
        __syncthreads();
        if (jt + 2 < nIter) kv_issue(jt + 2);

        const uint32_t kh_b = sb + AKV + (jt % 3) * AKV_STG;
        const uint32_t kl_b = kh_b + AMAT;
        const uint32_t vh_b = kh_b + 2 * AMAT;

        float sf[8][4];
#pragma unroll
        for (int jj = 0; jj < 8; jj++)
#pragma unroll
            for (int r = 0; r < 4; r++) sf[jj][r] = 0.f;

#pragma unroll
        for (int ks = 0; ks < 8; ks++) {
            const int k0 = ks * 16;
#pragma unroll
            for (int jb = 0; jb < 4; jb++) {
                uint32_t boff = (uint32_t)(((jb * 16 + lrow) * LDQ + k0 + lcolh) * 2);
                uint32_t bh[4], bl[4];
                LDSM_X4(bh[0], bh[1], bh[2], bh[3], kh_b + boff);
                LDSM_X4(bl[0], bl[1], bl[2], bl[3], kl_b + boff);
                MMA16816(sf[2 * jb], qfh[ks][0], qfh[ks][1], qfh[ks][2], qfh[ks][3], bh[0], bh[2]);
                MMA16816(sf[2 * jb], qfh[ks][0], qfh[ks][1], qfh[ks][2], qfh[ks][3], bl[0], bl[2]);
                MMA16816(sf[2 * jb], qfl[ks][0], qfl[ks][1], qfl[ks][2], qfl[ks][3], bh[0], bh[2]);
                MMA16816(sf[2 * jb + 1], qfh[ks][0], qfh[ks][1], qfh[ks][2], qfh[ks][3], bh[1], bh[3]);
                MMA16816(sf[2 * jb + 1], qfh[ks][0], qfh[ks][1], qfh[ks][2], qfh[ks][3], bl[1], bl[3]);
                MMA16816(sf[2 * jb + 1], qfl[ks][0], qfl[ks][1], qfl[ks][2], qfl[ks][3], bh[1], bh[3]);
            }
        }

        const int jn0 = jt * 64;
        float mx0 = -1e30f, mx1 = -1e30f;
#pragma unroll
        for (int jj = 0; jj < 8; jj++) {
            int cb = jn0 + jj * 8 + c0l;
            sf[jj][0] = (cb > gq0) ? -1e30f : sf[jj][0] * scale;
            sf[jj][1] = (cb + 1 > gq0) ? -1e30f : sf[jj][1] * scale;
            sf[jj][2] = (cb > gq1) ? -1e30f : sf[jj][2] * scale;
            sf[jj][3] = (cb + 1 > gq1) ? -1e30f : sf[jj][3] * scale;
            mx0 = fmaxf(mx0, fmaxf(sf[jj][0], sf[jj][1]));
            mx1 = fmaxf(mx1, fmaxf(sf[jj][2], sf[jj][3]));
        }
        mx0 = fmaxf(mx0, __shfl_xor_sync(0xFFFFFFFFu, mx0, 1));
        mx0 = fmaxf(mx0, __shfl_xor_sync(0xFFFFFFFFu, mx0, 2));
        mx1 = fmaxf(mx1, __shfl_xor_sync(0xFFFFFFFFu, mx1, 1));
        mx1 = fmaxf(mx1, __shfl_xor_sync(0xFFFFFFFFu, mx1, 2));
        const float mN0 = fmaxf(rM0, mx0), mN1 = fmaxf(rM1, mx1);
        const float corr0 = __expf(rM0 - mN0), corr1 = __expf(rM1 - mN1);
        rM0 = mN0; rM1 = mN1;

        float sum0 = 0.f, sum1 = 0.f;
        uint32_t Ph[4][4], Pl[4][4];
#pragma unroll
        for (int jj = 0; jj < 8; jj++) {
            float e0 = __expf(sf[jj][0] - mN0);
            float e1 = __expf(sf[jj][1] - mN0);
            float e2 = __expf(sf[jj][2] - mN1);
            float e3 = __expf(sf[jj][3] - mN1);
            sum0 += e0 + e1;
            sum1 += e2 + e3;
            __half h0 = __float2half_rn(e0), h1 = __float2half_rn(e1);
            __half h2 = __float2half_rn(e2), h3 = __float2half_rn(e3);
            const int kk = jj >> 1, q = (jj & 1) * 2;
            Ph[kk][q + 0] = pack_h2(h0, h1);
            Ph[kk][q + 1] = pack_h2(h2, h3);
            Pl[kk][q + 0] = pack_h2(__float2half_rn(e0 - __half2float(h0)),
                                    __float2half_rn(e1 - __half2float(h1)));
            Pl[kk][q + 1] = pack_h2(__float2half_rn(e2 - __half2float(h2)),
                                    __float2half_rn(e3 - __half2float(h3)));
        }
        sum0 += __shfl_xor_sync(0xFFFFFFFFu, sum0, 1);
        sum0 += __shfl_xor_sync(0xFFFFFFFFu, sum0, 2);
        sum1 += __shfl_xor_sync(0xFFFFFFFFu, sum1, 1);
        sum1 += __shfl_xor_sync(0xFFFFFFFFu, sum1, 2);
        rL0 = rL0 * corr0 + sum0;
        rL1 = rL1 * corr1 + sum1;

#pragma unroll
        for (int nf = 0; nf < 16; nf++) {
            o[nf][0] *= corr0; o[nf][1] *= corr0;
            o[nf][2] *= corr1; o[nf][3] *= corr1;
        }

#pragma unroll
        for (int kk = 0; kk < 4; kk++) {
            const int vk = kk * 16;
#pragma unroll
            for (int vx = 0; vx < 8; vx++) {
                const int d0 = vx * 16;
                uint32_t vo = (uint32_t)(((vk + lrow) * LDQ + d0 + lcolh) * 2);
                uint32_t vh[4];
                LDSM_X4T(vh[0], vh[1], vh[2], vh[3], vh_b + vo);
                MMA16816(o[2 * vx], Ph[kk][0], Ph[kk][1], Ph[kk][2], Ph[kk][3], vh[0], vh[1]);
                MMA16816(o[2 * vx], Pl[kk][0], Pl[kk][1], Pl[kk][2], Pl[kk][3], vh[0], vh[1]);
                MMA16816(o[2 * vx + 1], Ph[kk][0], Ph[kk][1], Ph[kk][2], Ph[kk][3], vh[2], vh[3]);
                MMA16816(o[2 * vx + 1], Pl[kk][0], Pl[kk][1], Pl[kk][2], Pl[kk][3], vh[2], vh[3]);
            }
        }
    }

    const float il0 = 1.f / rL0, il1 = 1.f / rL1;
#pragma unroll
    for (int nf = 0; nf < 16; nf++) {
        const int d = h * DH + nf * 8 + c0l;
        float f0 = o[nf][0] * il0, f1 = o[nf][1] * il0;
        float f2 = o[nf][2] * il1, f3 = o[nf][3] * il1;
        __half h0 = __float2half_rn(f0), h1 = __float2half_rn(f1);
        __half h2 = __float2half_rn(f2), h3 = __float2half_rn(f3);
        size_t o0 = (size_t)gq0 * HID_DIM + d;
        size_t o1 = (size_t)gq1 * HID_DIM + d;
        *(__half2*)(Oh + o0) = __halves2half2(h0, h1);
        *(__half2*)(Oh + o1) = __halves2half2(h2, h3);
        *(__half2*)(Ol + o0) = __halves2half2(
            __float2half_rn(f0 - __half2float(h0)),
            __float2half_rn(f1 - __half2float(h1)));
        *(__half2*)(Ol + o1) = __halves2half2(
            __float2half_rn(f2 - __half2float(h2)),
            __float2half_rn(f3 - __half2float(h3)));
    }
}

// ---------------------------------------------------------------------------
// Orchestration
// ---------------------------------------------------------------------------
extern "C" void kernel_launch(void* const* d_in, const int* in_sizes, int n_in,
                              void* d_out, int out_size)
{
    const float* hidden = (const float*)d_in[0];
    const float* wq = (const float*)d_in[2];
    const float* wk = (const float*)d_in[3];
    const float* wv = (const float*)d_in[4];
    const float* wo = (const float*)d_in[5];
    float* out = (float*)d_out;

    __half *hh, *hl, *qkvh, *qkvl, *ath, *atl, *wqkv, *wot;
    cudaGetSymbolAddress((void**)&hh, g_hid_hi);    cudaGetSymbolAddress((void**)&hl, g_hid_lo);
    cudaGetSymbolAddress((void**)&qkvh, g_qkv_hi);  cudaGetSymbolAddress((void**)&qkvl, g_qkv_lo);
    cudaGetSymbolAddress((void**)&ath, g_at_hi);    cudaGetSymbolAddress((void**)&atl, g_at_lo);
    cudaGetSymbolAddress((void**)&wqkv, g_wqkvT);   cudaGetSymbolAddress((void**)&wot, g_woT);

    cudaFuncSetAttribute(attn_mma_kernel, cudaFuncAttributeMaxDynamicSharedMemorySize, ATT_SMEM);
    cudaFuncSetAttribute(gemm_fp16x2_kernel, cudaFuncAttributeMaxDynamicSharedMemorySize, GEMM_SMEM);

    conv_hilo_kernel<<<(S_LEN * HID_DIM) / 1024, 256>>>(hidden, hh, hl, S_LEN * HID_DIM);
    dim3 tb(32, 8);
    conv_t_all_kernel<<<dim3(HID_DIM / 32, HID_DIM / 32, 4), tb>>>(
        wq, wk, wv, wo, wqkv, wot);

    gemm_fp16x2_kernel<<<dim3(QKVW / 256, S_LEN / 128), 512, GEMM_SMEM>>>(
        hh, hl, wqkv, nullptr, qkvh, qkvl, S_LEN, QKVW, HID_DIM);

    attn_mma_kernel<<<dim3(16, NH), 256, ATT_SMEM>>>(qkvh, qkvl, ath, atl);

    gemm_fp16x2_kernel<<<dim3(HID_DIM / 256, S_LEN / 128), 512, GEMM_SMEM>>>(
        ath, atl, wot, out, nullptr, nullptr, S_LEN, HID_DIM, HID_DIM);
}

// round 16
// speedup vs baseline: 1.0013x; 1.0013x over previous
#include <cuda_runtime.h>
#include <cuda_fp16.h>
#include <cstdint>
#include <math.h>

#define S_LEN 2048
#define HID_DIM 4096
#define NH 32
#define NKV 8
#define DH 128
#define KVW (NKV * DH)     // 1024
#define QKVW 6144          // fused Q(4096) + K(1024) + V(1024) width

// ---------------------------------------------------------------------------
// Scratch (device globals: allocation-free)
// ---------------------------------------------------------------------------
__device__ __half g_hid_hi[S_LEN * HID_DIM];
__device__ __half g_hid_lo[S_LEN * HID_DIM];
__device__ __half g_qkv_hi[S_LEN * QKVW];
__device__ __half g_qkv_lo[S_LEN * QKVW];
__device__ __half g_at_hi[S_LEN * HID_DIM];
__device__ __half g_at_lo[S_LEN * HID_DIM];
__device__ __half g_wqkvT[QKVW * HID_DIM];
__device__ __half g_woT[HID_DIM * HID_DIM];

// ---------------------------------------------------------------------------
// PTX helpers (baseline sm_80 PTX — safe on compute_103)
// ---------------------------------------------------------------------------
__device__ __forceinline__ uint32_t smem_u32(const void* p) {
    return (uint32_t)__cvta_generic_to_shared(p);
}
#define CP_ASYNC16(sa, gp) \
    asm volatile("cp.async.cg.shared.global [%0], [%1], 16;" :: "r"(sa), "l"(gp))
#define CP_COMMIT() asm volatile("cp.async.commit_group;" ::: "memory")
#define CP_WAIT(n)  asm volatile("cp.async.wait_group %0;" :: "n"(n) : "memory")

#define LDSM_X4(r0, r1, r2, r3, a) \
    asm volatile("ldmatrix.sync.aligned.m8n8.x4.shared.b16 {%0,%1,%2,%3},[%4];" \
        : "=r"(r0), "=r"(r1), "=r"(r2), "=r"(r3) : "r"(a))
#define LDSM_X4T(r0, r1, r2, r3, a) \
    asm volatile("ldmatrix.sync.aligned.m8n8.x4.trans.shared.b16 {%0,%1,%2,%3},[%4];" \
        : "=r"(r0), "=r"(r1), "=r"(r2), "=r"(r3) : "r"(a))
#define MMA16816(d, a0, a1, a2, a3, b0, b1) \
    asm volatile("mma.sync.aligned.m16n8k16.row.col.f32.f16.f16.f32 " \
        "{%0,%1,%2,%3},{%4,%5,%6,%7},{%8,%9},{%0,%1,%2,%3};" \
        : "+f"((d)[0]), "+f"((d)[1]), "+f"((d)[2]), "+f"((d)[3]) \
        : "r"(a0), "r"(a1), "r"(a2), "r"(a3), "r"(b0), "r"(b1))

__device__ __forceinline__ uint32_t pack_h2(__half a, __half b) {
    __half2 h = __halves2half2(a, b);
    return *(uint32_t*)&h;
}

// ---------------------------------------------------------------------------
// Split fp32 -> (hi, lo) fp16, elementwise
// ---------------------------------------------------------------------------
__global__ void conv_hilo_kernel(const float* __restrict__ x,
                                 __half* __restrict__ hi,
                                 __half* __restrict__ lo, int n)
{
    int i = (blockIdx.x * blockDim.x + threadIdx.x) * 4;
    if (i >= n) return;
    float4 v = *(const float4*)(x + i);
    __half h0 = __float2half_rn(v.x);
    __half h1 = __float2half_rn(v.y);
    __half h2 = __float2half_rn(v.z);
    __half h3 = __float2half_rn(v.w);
    __half l0 = __float2half_rn(v.x - __half2float(h0));
    __half l1 = __float2half_rn(v.y - __half2float(h1));
    __half l2 = __float2half_rn(v.z - __half2float(h2));
    __half l3 = __float2half_rn(v.w - __half2float(h3));
    __half2* hp = (__half2*)(hi + i);
    __half2* lp = (__half2*)(lo + i);
    hp[0] = __half2(h0, h1); hp[1] = __half2(h2, h3);
    lp[0] = __half2(l0, l1); lp[1] = __half2(l2, l3);
}

// ---------------------------------------------------------------------------
// Transpose + round all 4 weights in one launch (grid.z selects weight).
// ---------------------------------------------------------------------------
__global__ void conv_t_all_kernel(const float* __restrict__ wq,
                                  const float* __restrict__ wk,
                                  const float* __restrict__ wv,
                                  const float* __restrict__ wo,
                                  __half* __restrict__ wqkv,
                                  __half* __restrict__ wot)
{
    const int z = blockIdx.z;
    const float* B;
    __half* T;
    int N;
    if (z == 0)      { B = wq; T = wqkv;                                  N = HID_DIM; }
    else if (z == 1) { B = wk; T = wqkv + (size_t)HID_DIM * HID_DIM;      N = KVW; }
    else if (z == 2) { B = wv; T = wqkv + (size_t)(HID_DIM + KVW) * HID_DIM; N = KVW; }
    else             { B = wo; T = wot;                                   N = HID_DIM; }

    const int n0 = blockIdx.x * 32;
    if (n0 >= N) return;
    const int k0 = blockIdx.y * 32;

    __shared__ float t[32][33];
    const int tx = threadIdx.x, ty = threadIdx.y;
#pragma unroll
    for (int i = 0; i < 32; i += 8)
        t[ty + i][tx] = B[(size_t)(k0 + ty + i) * N + n0 + tx];
    __syncthreads();
#pragma unroll
    for (int i = 0; i < 32; i += 8) {
        size_t o = (size_t)(n0 + ty + i) * HID_DIM + k0 + tx;
        T[o] = __float2half_rn(t[tx][ty + i]);
    }
}

// ---------------------------------------------------------------------------
// Persistent fp16 split-A GEMM: D = Ah*B + Al*B.  B transposed [N,K] fp16.
// CTA tile 128x128, 8 warps (warp tile 32x64), k64 chunks, 2-stage cp.async
// (issue after sync), 2 CTAs/SM. 296 persistent CTAs loop over output tiles.
// ---------------------------------------------------------------------------
#define TLD 72
#define SMAT_BYTES (128 * TLD * 2)            // 18432
#define STG_BYTES (3 * SMAT_BYTES)            // 55296 (Ah, Al, B)
#define GEMM_SMEM (2 * STG_BYTES)             // 110592
#define GEMM_GRID 296

__global__ void __launch_bounds__(256, 2) gemm_fp16x2_kernel(
    const __half* __restrict__ Ahi, const __half* __restrict__ Alo,
    const __half* __restrict__ Bh,
    float* __restrict__ Cf,
    __half* __restrict__ Chi, __half* __restrict__ Clo,
    int M, int N, int K)
{
    extern __shared__ char smem[];
    const uint32_t sb = smem_u32(smem);
    const int tid = threadIdx.x;
    const int lane = tid & 31, wid = tid >> 5;
    const int wm = wid & 3, wn = wid >> 2;
    const int nx = N >> 7;
    const int nTiles = (M >> 7) * nx;
    const int nIter = K >> 6;

    for (int tile = blockIdx.x; tile < nTiles; tile += gridDim.x) {
        const int m0 = (tile / nx) * 128;
        const int n0 = (tile % nx) * 128;

        auto issue = [&](int it) {
            const uint32_t st = sb + (it & 1) * STG_BYTES;
            const int k0 = it * 64;
#pragma unroll
            for (int i = 0; i < 4; i++) {
                int c = tid + i * 256;           // 0..1023
                int row = c >> 3, seg = c & 7;
                uint32_t so = (uint32_t)((row * TLD + seg * 8) * 2);
                size_t gA = (size_t)(m0 + row) * K + k0 + seg * 8;
                size_t gB = (size_t)(n0 + row) * K + k0 + seg * 8;
                CP_ASYNC16(st + so, (const void*)(Ahi + gA));
                CP_ASYNC16(st + SMAT_BYTES + so, (const void*)(Alo + gA));
                CP_ASYNC16(st + 2 * SMAT_BYTES + so, (const void*)(Bh + gB));
            }
            CP_COMMIT();
        };

        float acc[2][8][4];
#pragma unroll
        for (int mi = 0; mi < 2; mi++)
#pragma unroll
            for (int nj = 0; nj < 8; nj++)
#pragma unroll
                for (int r = 0; r < 4; r++) acc[mi][nj][r] = 0.f;

        issue(0);

        for (int it = 0; it < nIter; ++it) {
            CP_WAIT(0);
            __syncthreads();
            if (it + 1 < nIter) issue(it + 1);   // after sync: other stage free

            const uint32_t st = sb + (it & 1) * STG_BYTES;
            const uint32_t ah_b = st;
            const uint32_t al_b = st + SMAT_BYTES;
            const uint32_t bh_b = st + 2 * SMAT_BYTES;

#pragma unroll
            for (int ks = 0; ks < 4; ks++) {
                uint32_t ah[2][4], al[2][4];
                const int arow = wm * 32 + (lane & 15);
                const int acol = ks * 16 + (lane >> 4) * 8;
#pragma unroll
                for (int mi = 0; mi < 2; mi++) {
                    uint32_t off = (uint32_t)(((arow + mi * 16) * TLD + acol) * 2);
                    LDSM_X4(ah[mi][0], ah[mi][1], ah[mi][2], ah[mi][3], ah_b + off);
                    LDSM_X4(al[mi][0], al[mi][1], al[mi][2], al[mi][3], al_b + off);
                }
                const int brow = wn * 64 + (lane & 7) + ((lane >> 4) << 3);
                const int bcol = ks * 16 + (((lane >> 3) & 1) << 3);
#pragma unroll
                for (int nt = 0; nt < 4; nt++) {
                    uint32_t off = (uint32_t)(((brow + nt * 16) * TLD + bcol) * 2);
                    uint32_t bh[4];
                    LDSM_X4(bh[0], bh[1], bh[2], bh[3], bh_b + off);
#pragma unroll
                    for (int mi = 0; mi < 2; mi++) {
                        MMA16816(acc[mi][2 * nt], ah[mi][0], ah[mi][1], ah[mi][2], ah[mi][3], bh[0], bh[1]);
                        MMA16816(acc[mi][2 * nt], al[mi][0], al[mi][1], al[mi][2], al[mi][3], bh[0], bh[1]);
                        MMA16816(acc[mi][2 * nt + 1], ah[mi][0], ah[mi][1], ah[mi][2], ah[mi][3], bh[2], bh[3]);
                        MMA16816(acc[mi][2 * nt + 1], al[mi][0], al[mi][1], al[mi][2], al[mi][3], bh[2], bh[3]);
                    }
                }
            }
        }

        const int er = lane >> 2, ec = (lane & 3) * 2;
#pragma unroll
        for (int mi = 0; mi < 2; mi++) {
            const int gr = m0 + wm * 32 + mi * 16 + er;
#pragma unroll
            for (int nj = 0; nj < 8; nj++) {
                const int gc = n0 + wn * 64 + nj * 8 + ec;
                if (Chi) {
#pragma unroll
                    for (int half_ = 0; half_ < 2; half_++) {
                        float f0 = acc[mi][nj][half_ * 2 + 0];
                        float f1 = acc[mi][nj][half_ * 2 + 1];
                        __half h0 = __float2half_rn(f0);
                        __half h1 = __float2half_rn(f1);
                        __half l0 = __float2half_rn(f0 - __half2float(h0));
                        __half l1 = __float2half_rn(f1 - __half2float(h1));
                        size_t o = (size_t)(gr + half_ * 8) * N + gc;
                        *(__half2*)(Chi + o) = __half2(h0, h1);
                        *(__half2*)(Clo + o) = __half2(l0, l1);
                    }
                } else {
                    *(float2*)(Cf + (size_t)gr * N + gc) =
                        make_float2(acc[mi][nj][0], acc[mi][nj][1]);
                    *(float2*)(Cf + (size_t)(gr + 8) * N + gc) =
                        make_float2(acc[mi][nj][2], acc[mi][nj][3]);
                }
            }
        }
    }
}

// ---------------------------------------------------------------------------
// FA2 attention (unchanged from R13): 8 warps x 16 rows, K 3-term, PV 2-term,
// Q frags hoisted, 3-stage KV pipeline.
// ---------------------------------------------------------------------------
#define LDQ 136
#define AQH 0
#define AQL 34816
#define AKV 69632
#define AMAT 17408
#define AKV_STG (3 * AMAT)            // 52224 (Kh, Kl, Vh)
#define ATT_SMEM (AKV + 3 * AKV_STG)  // 226304

__global__ void __launch_bounds__(256, 1) attn_mma_kernel(
    const __half* __restrict__ QKVh, const __half* __restrict__ QKVl,
    __half* __restrict__ Oh, __half* __restrict__ Ol)
{
    extern __shared__ char sm[];
    const uint32_t sb = smem_u32(sm);
    const int tid = threadIdx.x;
    const int wid = tid >> 5, lane = tid & 31;
    const int qt = 15 - (int)blockIdx.x;     // heavy tiles first
    const int h = blockIdx.y;
    const int kvh = h >> 2;
    const int m0 = qt * 128;
    const int wrow = wid * 16;
    const float scale = 0.08838834764831845f;

    const int koff = HID_DIM + kvh * DH;
    const int voff = HID_DIM + KVW + kvh * DH;

    auto kv_issue = [&](int jt) {
        const uint32_t st = sb + AKV + (jt % 3) * AKV_STG;
#pragma unroll
        for (int i = 0; i < 4; i++) {
            int idx = tid + i * 256;
            int row = idx >> 4, seg = idx & 15;
            uint32_t so = (uint32_t)((row * LDQ + seg * 8) * 2);
            size_t gK = (size_t)(jt * 64 + row) * QKVW + koff + seg * 8;
            size_t gV = (size_t)(jt * 64 + row) * QKVW + voff + seg * 8;
            CP_ASYNC16(st + 0 * AMAT + so, (const void*)(QKVh + gK));
            CP_ASYNC16(st + 1 * AMAT + so, (const void*)(QKVl + gK));
            CP_ASYNC16(st + 2 * AMAT + so, (const void*)(QKVh + gV));
        }
        CP_COMMIT();
    };

    const int nIter = 2 * qt + 2;
    kv_issue(0);

    {
        __half* qh_s = (__half*)(sm + AQH);
        __half* ql_s = (__half*)(sm + AQL);
#pragma unroll
        for (int i = 0; i < 8; i++) {
            int idx = tid + i * 256;
            int row = idx >> 4, seg = idx & 15;
            size_t g = (size_t)(m0 + row) * QKVW + h * DH + seg * 8;
            *(uint4*)(qh_s + row * LDQ + seg * 8) = *(const uint4*)(QKVh + g);
            *(uint4*)(ql_s + row * LDQ + seg * 8) = *(const uint4*)(QKVl + g);
        }
    }
    if (nIter > 1) kv_issue(1);
    __syncthreads();

    const int lrow = lane & 15, lcolh = (lane >> 4) * 8;
    uint32_t qfh[8][4], qfl[8][4];
#pragma unroll
    for (int ks = 0; ks < 8; ks++) {
        uint32_t aoff = (uint32_t)(((wrow + lrow) * LDQ + ks * 16 + lcolh) * 2);
        LDSM_X4(qfh[ks][0], qfh[ks][1], qfh[ks][2], qfh[ks][3], sb + AQH + aoff);
        LDSM_X4(qfl[ks][0], qfl[ks][1], qfl[ks][2], qfl[ks][3], sb + AQL + aoff);
    }

    float o[16][4];
#pragma unroll
    for (int nf = 0; nf < 16; nf++)
#pragma unroll
        for (int r = 0; r < 4; r++) o[nf][r] = 0.f;
    float rM0 = -1e30f, rM1 = -1e30f, rL0 = 0.f, rL1 = 0.f;

    const int r0l = lane >> 2, c0l = (lane & 3) * 2;
    const int gq0 = m0 + wrow + r0l, gq1 = gq0 + 8;

    for (int jt = 0; jt < nIter; jt++) {
        if (jt + 1 < nIter) { CP_WAIT(1); } else { CP_WAIT(0); }
        __syncthreads();
        if (jt + 2 < nIter) kv_issue(jt + 2);

        const uint32_t kh_b = sb + AKV + (jt % 3) * AKV_STG;
        const uint32_t kl_b = kh_b + AMAT;
        const uint32_t vh_b = kh_b + 2 * AMAT;

        float sf[8][4];
#pragma unroll
        for (int jj = 0; jj < 8; jj++)
#pragma unroll
            for (int r = 0; r < 4; r++) sf[jj][r] = 0.f;

#pragma unroll
        for (int ks = 0; ks < 8; ks++) {
            const int k0 = ks * 16;
#pragma unroll
            for (int jb = 0; jb < 4; jb++) {
                uint32_t boff = (uint32_t)(((jb * 16 + lrow) * LDQ + k0 + lcolh) * 2);
                uint32_t bh[4], bl[4];
                LDSM_X4(bh[0], bh[1], bh[2], bh[3], kh_b + boff);
                LDSM_X4(bl[0], bl[1], bl[2], bl[3], kl_b + boff);
                MMA16816(sf[2 * jb], qfh[ks][0], qfh[ks][1], qfh[ks][2], qfh[ks][3], bh[0], bh[2]);
                MMA16816(sf[2 * jb], qfh[ks][0], qfh[ks][1], qfh[ks][2], qfh[ks][3], bl[0], bl[2]);
                MMA16816(sf[2 * jb], qfl[ks][0], qfl[ks][1], qfl[ks][2], qfl[ks][3], bh[0], bh[2]);
                MMA16816(sf[2 * jb + 1], qfh[ks][0], qfh[ks][1], qfh[ks][2], qfh[ks][3], bh[1], bh[3]);
                MMA16816(sf[2 * jb + 1], qfh[ks][0], qfh[ks][1], qfh[ks][2], qfh[ks][3], bl[1], bl[3]);
                MMA16816(sf[2 * jb + 1], qfl[ks][0], qfl[ks][1], qfl[ks][2], qfl[ks][3], bh[1], bh[3]);
            }
        }

        const int jn0 = jt * 64;
        float mx0 = -1e30f, mx1 = -1e30f;
#pragma unroll
        for (int jj = 0; jj < 8; jj++) {
            int cb = jn0 + jj * 8 + c0l;
            sf[jj][0] = (cb > gq0) ? -1e30f : sf[jj][0] * scale;
            sf[jj][1] = (cb + 1 > gq0) ? -1e30f : sf[jj][1] * scale;
            sf[jj][2] = (cb > gq1) ? -1e30f : sf[jj][2] * scale;
            sf[jj][3] = (cb + 1 > gq1) ? -1e30f : sf[jj][3] * scale;
            mx0 = fmaxf(mx0, fmaxf(sf[jj][0], sf[jj][1]));
            mx1 = fmaxf(mx1, fmaxf(sf[jj][2], sf[jj][3]));
        }
        mx0 = fmaxf(mx0, __shfl_xor_sync(0xFFFFFFFFu, mx0, 1));
        mx0 = fmaxf(mx0, __shfl_xor_sync(0xFFFFFFFFu, mx0, 2));
        mx1 = fmaxf(mx1, __shfl_xor_sync(0xFFFFFFFFu, mx1, 1));
        mx1 = fmaxf(mx1, __shfl_xor_sync(0xFFFFFFFFu, mx1, 2));
        const float mN0 = fmaxf(rM0, mx0), mN1 = fmaxf(rM1, mx1);
        const float corr0 = __expf(rM0 - mN0), corr1 = __expf(rM1 - mN1);
        rM0 = mN0; rM1 = mN1;

        float sum0 = 0.f, sum1 = 0.f;
        uint32_t Ph[4][4], Pl[4][4];
#pragma unroll
        for (int jj = 0; jj < 8; jj++) {
            float e0 = __expf(sf[jj][0] - mN0);
            float e1 = __expf(sf[jj][1] - mN0);
            float e2 = __expf(sf[jj][2] - mN1);
            float e3 = __expf(sf[jj][3] - mN1);
            sum0 += e0 + e1;
            sum1 += e2 + e3;
            __half h0 = __float2half_rn(e0), h1 = __float2half_rn(e1);
            __half h2 = __float2half_rn(e2), h3 = __float2half_rn(e3);
            const int kk = jj >> 1, q = (jj & 1) * 2;
            Ph[kk][q + 0] = pack_h2(h0, h1);
            Ph[kk][q + 1] = pack_h2(h2, h3);
            Pl[kk][q + 0] = pack_h2(__float2half_rn(e0 - __half2float(h0)),
                                    __float2half_rn(e1 - __half2float(h1)));
            Pl[kk][q + 1] = pack_h2(__float2half_rn(e2 - __half2float(h2)),
                                    __float2half_rn(e3 - __half2float(h3)));
        }
        sum0 += __shfl_xor_sync(0xFFFFFFFFu, sum0, 1);
        sum0 += __shfl_xor_sync(0xFFFFFFFFu, sum0, 2);
        sum1 += __shfl_xor_sync(0xFFFFFFFFu, sum1, 1);
        sum1 += __shfl_xor_sync(0xFFFFFFFFu, sum1, 2);
        rL0 = rL0 * corr0 + sum0;
        rL1 = rL1 * corr1 + sum1;

#pragma unroll
        for (int nf = 0; nf < 16; nf++) {
            o[nf][0] *= corr0; o[nf][1] *= corr0;
            o[nf][2] *= corr1; o[nf][3] *= corr1;
        }

#pragma unroll
        for (int kk = 0; kk < 4; kk++) {
            const int vk = kk * 16;
#pragma unroll
            for (int vx = 0; vx < 8; vx++) {
                const int d0 = vx * 16;
                uint32_t vo = (uint32_t)(((vk + lrow) * LDQ + d0 + lcolh) * 2);
                uint32_t vh[4];
                LDSM_X4T(vh[0], vh[1], vh[2], vh[3], vh_b + vo);
                MMA16816(o[2 * vx], Ph[kk][0], Ph[kk][1], Ph[kk][2], Ph[kk][3], vh[0], vh[1]);
                MMA16816(o[2 * vx], Pl[kk][0], Pl[kk][1], Pl[kk][2], Pl[kk][3], vh[0], vh[1]);
                MMA16816(o[2 * vx + 1], Ph[kk][0], Ph[kk][1], Ph[kk][2], Ph[kk][3], vh[2], vh[3]);
                MMA16816(o[2 * vx + 1], Pl[kk][0], Pl[kk][1], Pl[kk][2], Pl[kk][3], vh[2], vh[3]);
            }
        }
    }

    const float il0 = 1.f / rL0, il1 = 1.f / rL1;
#pragma unroll
    for (int nf = 0; nf < 16; nf++) {
        const int d = h * DH + nf * 8 + c0l;
        float f0 = o[nf][0] * il0, f1 = o[nf][1] * il0;
        float f2 = o[nf][2] * il1, f3 = o[nf][3] * il1;
        __half h0 = __float2half_rn(f0), h1 = __float2half_rn(f1);
        __half h2 = __float2half_rn(f2), h3 = __float2half_rn(f3);
        size_t o0 = (size_t)gq0 * HID_DIM + d;
        size_t o1 = (size_t)gq1 * HID_DIM + d;
        *(__half2*)(Oh + o0) = __halves2half2(h0, h1);
        *(__half2*)(Oh + o1) = __halves2half2(h2, h3);
        *(__half2*)(Ol + o0) = __halves2half2(
            __float2half_rn(f0 - __half2float(h0)),
            __float2half_rn(f1 - __half2float(h1)));
        *(__half2*)(Ol + o1) = __halves2half2(
            __float2half_rn(f2 - __half2float(h2)),
            __float2half_rn(f3 - __half2float(h3)));
    }
}

// ---------------------------------------------------------------------------
// Orchestration
// ---------------------------------------------------------------------------
extern "C" void kernel_launch(void* const* d_in, const int* in_sizes, int n_in,
                              void* d_out, int out_size)
{
    const float* hidden = (const float*)d_in[0];
    const float* wq = (const float*)d_in[2];
    const float* wk = (const float*)d_in[3];
    const float* wv = (const float*)d_in[4];
    const float* wo = (const float*)d_in[5];
    float* out = (float*)d_out;

    __half *hh, *hl, *qkvh, *qkvl, *ath, *atl, *wqkv, *wot;
    cudaGetSymbolAddress((void**)&hh, g_hid_hi);    cudaGetSymbolAddress((void**)&hl, g_hid_lo);
    cudaGetSymbolAddress((void**)&qkvh, g_qkv_hi);  cudaGetSymbolAddress((void**)&qkvl, g_qkv_lo);
    cudaGetSymbolAddress((void**)&ath, g_at_hi);    cudaGetSymbolAddress((void**)&atl, g_at_lo);
    cudaGetSymbolAddress((void**)&wqkv, g_wqkvT);   cudaGetSymbolAddress((void**)&wot, g_woT);

    cudaFuncSetAttribute(attn_mma_kernel, cudaFuncAttributeMaxDynamicSharedMemorySize, ATT_SMEM);
    cudaFuncSetAttribute(gemm_fp16x2_kernel, cudaFuncAttributeMaxDynamicSharedMemorySize, GEMM_SMEM);

    conv_hilo_kernel<<<(S_LEN * HID_DIM) / 1024, 256>>>(hidden, hh, hl, S_LEN * HID_DIM);
    dim3 tb(32, 8);
    conv_t_all_kernel<<<dim3(HID_DIM / 32, HID_DIM / 32, 4), tb>>>(
        wq, wk, wv, wo, wqkv, wot);

    gemm_fp16x2_kernel<<<GEMM_GRID, 256, GEMM_SMEM>>>(
        hh, hl, wqkv, nullptr, qkvh, qkvl, S_LEN, QKVW, HID_DIM);

    attn_mma_kernel<<<dim3(16, NH), 256, ATT_SMEM>>>(qkvh, qkvl, ath, atl);

    gemm_fp16x2_kernel<<<GEMM_GRID, 256, GEMM_SMEM>>>(
        ath, atl, wot, out, nullptr, nullptr, S_LEN, HID_DIM, HID_DIM);
}

// round 17
// speedup vs baseline: 1.0530x; 1.0516x over previous
#include <cuda_runtime.h>
#include <cuda_fp16.h>
#include <cstdint>
#include <math.h>

#define S_LEN 2048
#define HID_DIM 4096
#define NH 32
#define NKV 8
#define DH 128
#define KVW (NKV * DH)     // 1024
#define QKVW 6144          // fused Q(4096) + K(1024) + V(1024) width

// ---------------------------------------------------------------------------
// Scratch (device globals: allocation-free)
// ---------------------------------------------------------------------------
__device__ __half g_hid_hi[S_LEN * HID_DIM];
__device__ __half g_hid_lo[S_LEN * HID_DIM];
__device__ __half g_qkv_hi[S_LEN * QKVW];
__device__ __half g_qkv_lo[S_LEN * QKVW];
__device__ __half g_at_hi[S_LEN * HID_DIM];
__device__ __half g_at_lo[S_LEN * HID_DIM];
__device__ __half g_wqkvT[QKVW * HID_DIM];
__device__ __half g_woT[HID_DIM * HID_DIM];

// ---------------------------------------------------------------------------
// PTX helpers (baseline sm_80 PTX — safe on compute_103)
// ---------------------------------------------------------------------------
__device__ __forceinline__ uint32_t smem_u32(const void* p) {
    return (uint32_t)__cvta_generic_to_shared(p);
}
#define CP_ASYNC16(sa, gp) \
    asm volatile("cp.async.cg.shared.global [%0], [%1], 16;" :: "r"(sa), "l"(gp))
#define CP_COMMIT() asm volatile("cp.async.commit_group;" ::: "memory")
#define CP_WAIT(n)  asm volatile("cp.async.wait_group %0;" :: "n"(n) : "memory")

#define LDSM_X4(r0, r1, r2, r3, a) \
    asm volatile("ldmatrix.sync.aligned.m8n8.x4.shared.b16 {%0,%1,%2,%3},[%4];" \
        : "=r"(r0), "=r"(r1), "=r"(r2), "=r"(r3) : "r"(a))
#define LDSM_X4T(r0, r1, r2, r3, a) \
    asm volatile("ldmatrix.sync.aligned.m8n8.x4.trans.shared.b16 {%0,%1,%2,%3},[%4];" \
        : "=r"(r0), "=r"(r1), "=r"(r2), "=r"(r3) : "r"(a))
#define MMA16816(d, a0, a1, a2, a3, b0, b1) \
    asm volatile("mma.sync.aligned.m16n8k16.row.col.f32.f16.f16.f32 " \
        "{%0,%1,%2,%3},{%4,%5,%6,%7},{%8,%9},{%0,%1,%2,%3};" \
        : "+f"((d)[0]), "+f"((d)[1]), "+f"((d)[2]), "+f"((d)[3]) \
        : "r"(a0), "r"(a1), "r"(a2), "r"(a3), "r"(b0), "r"(b1))

__device__ __forceinline__ uint32_t pack_h2(__half a, __half b) {
    __half2 h = __halves2half2(a, b);
    return *(uint32_t*)&h;
}

// ---------------------------------------------------------------------------
// Split fp32 -> (hi, lo) fp16, elementwise
// ---------------------------------------------------------------------------
__global__ void conv_hilo_kernel(const float* __restrict__ x,
                                 __half* __restrict__ hi,
                                 __half* __restrict__ lo, int n)
{
    int i = (blockIdx.x * blockDim.x + threadIdx.x) * 4;
    if (i >= n) return;
    float4 v = *(const float4*)(x + i);
    __half h0 = __float2half_rn(v.x);
    __half h1 = __float2half_rn(v.y);
    __half h2 = __float2half_rn(v.z);
    __half h3 = __float2half_rn(v.w);
    __half l0 = __float2half_rn(v.x - __half2float(h0));
    __half l1 = __float2half_rn(v.y - __half2float(h1));
    __half l2 = __float2half_rn(v.z - __half2float(h2));
    __half l3 = __float2half_rn(v.w - __half2float(h3));
    __half2* hp = (__half2*)(hi + i);
    __half2* lp = (__half2*)(lo + i);
    hp[0] = __half2(h0, h1); hp[1] = __half2(h2, h3);
    lp[0] = __half2(l0, l1); lp[1] = __half2(l2, l3);
}

// ---------------------------------------------------------------------------
// Transpose + round all 4 weights in one launch (grid.z selects weight).
// ---------------------------------------------------------------------------
__global__ void conv_t_all_kernel(const float* __restrict__ wq,
                                  const float* __restrict__ wk,
                                  const float* __restrict__ wv,
                                  const float* __restrict__ wo,
                                  __half* __restrict__ wqkv,
                                  __half* __restrict__ wot)
{
    const int z = blockIdx.z;
    const float* B;
    __half* T;
    int N;
    if (z == 0)      { B = wq; T = wqkv;                                  N = HID_DIM; }
    else if (z == 1) { B = wk; T = wqkv + (size_t)HID_DIM * HID_DIM;      N = KVW; }
    else if (z == 2) { B = wv; T = wqkv + (size_t)(HID_DIM + KVW) * HID_DIM; N = KVW; }
    else             { B = wo; T = wot;                                   N = HID_DIM; }

    const int n0 = blockIdx.x * 32;
    if (n0 >= N) return;
    const int k0 = blockIdx.y * 32;

    __shared__ float t[32][33];
    const int tx = threadIdx.x, ty = threadIdx.y;
#pragma unroll
    for (int i = 0; i < 32; i += 8)
        t[ty + i][tx] = B[(size_t)(k0 + ty + i) * N + n0 + tx];
    __syncthreads();
#pragma unroll
    for (int i = 0; i < 32; i += 8) {
        size_t o = (size_t)(n0 + ty + i) * HID_DIM + k0 + tx;
        T[o] = __float2half_rn(t[tx][ty + i]);
    }
}

// ---------------------------------------------------------------------------
// fp16 split-A GEMM (R13 config, the proven best): D = Ah*B + Al*B.
// CTA tile 128x128, 8 warps (warp tile 32x64), k64 chunks, 2-stage cp.async
// (issue after sync — race-free), 2 CTAs/SM.
// ---------------------------------------------------------------------------
#define TLD 72
#define SMAT_BYTES (128 * TLD * 2)            // 18432
#define STG_BYTES (3 * SMAT_BYTES)            // 55296 (Ah, Al, B)
#define GEMM_SMEM (2 * STG_BYTES)             // 110592

__global__ void __launch_bounds__(256, 2) gemm_fp16x2_kernel(
    const __half* __restrict__ Ahi, const __half* __restrict__ Alo,
    const __half* __restrict__ Bh,
    float* __restrict__ Cf,
    __half* __restrict__ Chi, __half* __restrict__ Clo,
    int M, int N, int K)
{
    extern __shared__ char smem[];
    const uint32_t sb = smem_u32(smem);
    const int tid = threadIdx.x;
    const int lane = tid & 31, wid = tid >> 5;
    const int wm = wid & 3, wn = wid >> 2;
    const int m0 = blockIdx.y * 128, n0 = blockIdx.x * 128;

    auto issue = [&](int it) {
        const uint32_t st = sb + (it & 1) * STG_BYTES;
        const int k0 = it * 64;
#pragma unroll
        for (int i = 0; i < 4; i++) {
            int c = tid + i * 256;           // 0..1023
            int row = c >> 3, seg = c & 7;
            uint32_t so = (uint32_t)((row * TLD + seg * 8) * 2);
            size_t gA = (size_t)(m0 + row) * K + k0 + seg * 8;
            size_t gB = (size_t)(n0 + row) * K + k0 + seg * 8;
            CP_ASYNC16(st + so, (const void*)(Ahi + gA));
            CP_ASYNC16(st + SMAT_BYTES + so, (const void*)(Alo + gA));
            CP_ASYNC16(st + 2 * SMAT_BYTES + so, (const void*)(Bh + gB));
        }
        CP_COMMIT();
    };

    float acc[2][8][4];
#pragma unroll
    for (int mi = 0; mi < 2; mi++)
#pragma unroll
        for (int nj = 0; nj < 8; nj++)
#pragma unroll
            for (int r = 0; r < 4; r++) acc[mi][nj][r] = 0.f;

    const int nIter = K >> 6;
    issue(0);

    for (int it = 0; it < nIter; ++it) {
        CP_WAIT(0);
        __syncthreads();
        if (it + 1 < nIter) issue(it + 1);   // after sync: other stage is free

        const uint32_t st = sb + (it & 1) * STG_BYTES;
        const uint32_t ah_b = st;
        const uint32_t al_b = st + SMAT_BYTES;
        const uint32_t bh_b = st + 2 * SMAT_BYTES;

#pragma unroll
        for (int ks = 0; ks < 4; ks++) {
            uint32_t ah[2][4], al[2][4];
            const int arow = wm * 32 + (lane & 15);
            const int acol = ks * 16 + (lane >> 4) * 8;
#pragma unroll
            for (int mi = 0; mi < 2; mi++) {
                uint32_t off = (uint32_t)(((arow + mi * 16) * TLD + acol) * 2);
                LDSM_X4(ah[mi][0], ah[mi][1], ah[mi][2], ah[mi][3], ah_b + off);
                LDSM_X4(al[mi][0], al[mi][1], al[mi][2], al[mi][3], al_b + off);
            }
            const int brow = wn * 64 + (lane & 7) + ((lane >> 4) << 3);
            const int bcol = ks * 16 + (((lane >> 3) & 1) << 3);
#pragma unroll
            for (int nt = 0; nt < 4; nt++) {
                uint32_t off = (uint32_t)(((brow + nt * 16) * TLD + bcol) * 2);
                uint32_t bh[4];
                LDSM_X4(bh[0], bh[1], bh[2], bh[3], bh_b + off);
#pragma unroll
                for (int mi = 0; mi < 2; mi++) {
                    MMA16816(acc[mi][2 * nt], ah[mi][0], ah[mi][1], ah[mi][2], ah[mi][3], bh[0], bh[1]);
                    MMA16816(acc[mi][2 * nt], al[mi][0], al[mi][1], al[mi][2], al[mi][3], bh[0], bh[1]);
                    MMA16816(acc[mi][2 * nt + 1], ah[mi][0], ah[mi][1], ah[mi][2], ah[mi][3], bh[2], bh[3]);
                    MMA16816(acc[mi][2 * nt + 1], al[mi][0], al[mi][1], al[mi][2], al[mi][3], bh[2], bh[3]);
                }
            }
        }
    }

    const int er = lane >> 2, ec = (lane & 3) * 2;
#pragma unroll
    for (int mi = 0; mi < 2; mi++) {
        const int gr = m0 + wm * 32 + mi * 16 + er;
#pragma unroll
        for (int nj = 0; nj < 8; nj++) {
            const int gc = n0 + wn * 64 + nj * 8 + ec;
            if (Chi) {
#pragma unroll
                for (int half_ = 0; half_ < 2; half_++) {
                    float f0 = acc[mi][nj][half_ * 2 + 0];
                    float f1 = acc[mi][nj][half_ * 2 + 1];
                    __half h0 = __float2half_rn(f0);
                    __half h1 = __float2half_rn(f1);
                    __half l0 = __float2half_rn(f0 - __half2float(h0));
                    __half l1 = __float2half_rn(f1 - __half2float(h1));
                    size_t o = (size_t)(gr + half_ * 8) * N + gc;
                    *(__half2*)(Chi + o) = __half2(h0, h1);
                    *(__half2*)(Clo + o) = __half2(l0, l1);
                }
            } else {
                *(float2*)(Cf + (size_t)gr * N + gc) =
                    make_float2(acc[mi][nj][0], acc[mi][nj][1]);
                *(float2*)(Cf + (size_t)(gr + 8) * N + gc) =
                    make_float2(acc[mi][nj][2], acc[mi][nj][3]);
            }
        }
    }
}

// ---------------------------------------------------------------------------
// FA2 attention: 8 warps x 16 rows, K 3-term, PV 1-term (P-hi x V-hi only;
// P-lo dropped — probs' fp16 rounding adds ~1.4e-4 rel, random sign).
// Q frags hoisted, 3-stage KV pipeline.
// ---------------------------------------------------------------------------
#define LDQ 136
#define AQH 0
#define AQL 34816
#define AKV 69632
#define AMAT 17408
#define AKV_STG (3 * AMAT)            // 52224 (Kh, Kl, Vh)
#define ATT_SMEM (AKV + 3 * AKV_STG)  // 226304

__global__ void __launch_bounds__(256, 1) attn_mma_kernel(
    const __half* __restrict__ QKVh, const __half* __restrict__ QKVl,
    __half* __restrict__ Oh, __half* __restrict__ Ol)
{
    extern __shared__ char sm[];
    const uint32_t sb = smem_u32(sm);
    const int tid = threadIdx.x;
    const int wid = tid >> 5, lane = tid & 31;
    const int qt = 15 - (int)blockIdx.x;     // heavy tiles first
    const int h = blockIdx.y;
    const int kvh = h >> 2;
    const int m0 = qt * 128;
    const int wrow = wid * 16;
    const float scale = 0.08838834764831845f;

    const int koff = HID_DIM + kvh * DH;
    const int voff = HID_DIM + KVW + kvh * DH;

    auto kv_issue = [&](int jt) {
        const uint32_t st = sb + AKV + (jt % 3) * AKV_STG;
#pragma unroll
        for (int i = 0; i < 4; i++) {
            int idx = tid + i * 256;
            int row = idx >> 4, seg = idx & 15;
            uint32_t so = (uint32_t)((row * LDQ + seg * 8) * 2);
            size_t gK = (size_t)(jt * 64 + row) * QKVW + koff + seg * 8;
            size_t gV = (size_t)(jt * 64 + row) * QKVW + voff + seg * 8;
            CP_ASYNC16(st + 0 * AMAT + so, (const void*)(QKVh + gK));
            CP_ASYNC16(st + 1 * AMAT + so, (const void*)(QKVl + gK));
            CP_ASYNC16(st + 2 * AMAT + so, (const void*)(QKVh + gV));
        }
        CP_COMMIT();
    };

    const int nIter = 2 * qt + 2;
    kv_issue(0);

    {
        __half* qh_s = (__half*)(sm + AQH);
        __half* ql_s = (__half*)(sm + AQL);
#pragma unroll
        for (int i = 0; i < 8; i++) {
            int idx = tid + i * 256;
            int row = idx >> 4, seg = idx & 15;
            size_t g = (size_t)(m0 + row) * QKVW + h * DH + seg * 8;
            *(uint4*)(qh_s + row * LDQ + seg * 8) = *(const uint4*)(QKVh + g);
            *(uint4*)(ql_s + row * LDQ + seg * 8) = *(const uint4*)(QKVl + g);
        }
    }
    if (nIter > 1) kv_issue(1);
    __syncthreads();

    const int lrow = lane & 15, lcolh = (lane >> 4) * 8;
    uint32_t qfh[8][4], qfl[8][4];
#pragma unroll
    for (int ks = 0; ks < 8; ks++) {
        uint32_t aoff = (uint32_t)(((wrow + lrow) * LDQ + ks * 16 + lcolh) * 2);
        LDSM_X4(qfh[ks][0], qfh[ks][1], qfh[ks][2], qfh[ks][3], sb + AQH + aoff);
        LDSM_X4(qfl[ks][0], qfl[ks][1], qfl[ks][2], qfl[ks][3], sb + AQL + aoff);
    }

    float o[16][4];
#pragma unroll
    for (int nf = 0; nf < 16; nf++)
#pragma unroll
        for (int r = 0; r < 4; r++) o[nf][r] = 0.f;
    float rM0 = -1e30f, rM1 = -1e30f, rL0 = 0.f, rL1 = 0.f;

    const int r0l = lane >> 2, c0l = (lane & 3) * 2;
    const int gq0 = m0 + wrow + r0l, gq1 = gq0 + 8;

    for (int jt = 0; jt < nIter; jt++) {
        if (jt + 1 < nIter) { CP_WAIT(1); } else { CP_WAIT(0); }
        __syncthreads();
        if (jt + 2 < nIter) kv_issue(jt + 2);

        const uint32_t kh_b = sb + AKV + (jt % 3) * AKV_STG;
        const uint32_t kl_b = kh_b + AMAT;
        const uint32_t vh_b = kh_b + 2 * AMAT;

        float sf[8][4];
#pragma unroll
        for (int jj = 0; jj < 8; jj++)
#pragma unroll
            for (int r = 0; r < 4; r++) sf[jj][r] = 0.f;

#pragma unroll
        for (int ks = 0; ks < 8; ks++) {
            const int k0 = ks * 16;
#pragma unroll
            for (int jb = 0; jb < 4; jb++) {
                uint32_t boff = (uint32_t)(((jb * 16 + lrow) * LDQ + k0 + lcolh) * 2);
                uint32_t bh[4], bl[4];
                LDSM_X4(bh[0], bh[1], bh[2], bh[3], kh_b + boff);
                LDSM_X4(bl[0], bl[1], bl[2], bl[3], kl_b + boff);
                MMA16816(sf[2 * jb], qfh[ks][0], qfh[ks][1], qfh[ks][2], qfh[ks][3], bh[0], bh[2]);
                MMA16816(sf[2 * jb], qfh[ks][0], qfh[ks][1], qfh[ks][2], qfh[ks][3], bl[0], bl[2]);
                MMA16816(sf[2 * jb], qfl[ks][0], qfl[ks][1], qfl[ks][2], qfl[ks][3], bh[0], bh[2]);
                MMA16816(sf[2 * jb + 1], qfh[ks][0], qfh[ks][1], qfh[ks][2], qfh[ks][3], bh[1], bh[3]);
                MMA16816(sf[2 * jb + 1], qfh[ks][0], qfh[ks][1], qfh[ks][2], qfh[ks][3], bl[1], bl[3]);
                MMA16816(sf[2 * jb + 1], qfl[ks][0], qfl[ks][1], qfl[ks][2], qfl[ks][3], bh[1], bh[3]);
            }
        }

        const int jn0 = jt * 64;
        float mx0 = -1e30f, mx1 = -1e30f;
#pragma unroll
        for (int jj = 0; jj < 8; jj++) {
            int cb = jn0 + jj * 8 + c0l;
            sf[jj][0] = (cb > gq0) ? -1e30f : sf[jj][0] * scale;
            sf[jj][1] = (cb + 1 > gq0) ? -1e30f : sf[jj][1] * scale;
            sf[jj][2] = (cb > gq1) ? -1e30f : sf[jj][2] * scale;
            sf[jj][3] = (cb + 1 > gq1) ? -1e30f : sf[jj][3] * scale;
            mx0 = fmaxf(mx0, fmaxf(sf[jj][0], sf[jj][1]));
            mx1 = fmaxf(mx1, fmaxf(sf[jj][2], sf[jj][3]));
        }
        mx0 = fmaxf(mx0, __shfl_xor_sync(0xFFFFFFFFu, mx0, 1));
        mx0 = fmaxf(mx0, __shfl_xor_sync(0xFFFFFFFFu, mx0, 2));
        mx1 = fmaxf(mx1, __shfl_xor_sync(0xFFFFFFFFu, mx1, 1));
        mx1 = fmaxf(mx1, __shfl_xor_sync(0xFFFFFFFFu, mx1, 2));
        const float mN0 = fmaxf(rM0, mx0), mN1 = fmaxf(rM1, mx1);
        const float corr0 = __expf(rM0 - mN0), corr1 = __expf(rM1 - mN1);
        rM0 = mN0; rM1 = mN1;

        float sum0 = 0.f, sum1 = 0.f;
        uint32_t Ph[4][4];
#pragma unroll
        for (int jj = 0; jj < 8; jj++) {
            float e0 = __expf(sf[jj][0] - mN0);
            float e1 = __expf(sf[jj][1] - mN0);
            float e2 = __expf(sf[jj][2] - mN1);
            float e3 = __expf(sf[jj][3] - mN1);
            sum0 += e0 + e1;
            sum1 += e2 + e3;
            const int kk = jj >> 1, q = (jj & 1) * 2;
            Ph[kk][q + 0] = pack_h2(__float2half_rn(e0), __float2half_rn(e1));
            Ph[kk][q + 1] = pack_h2(__float2half_rn(e2), __float2half_rn(e3));
        }
        sum0 += __shfl_xor_sync(0xFFFFFFFFu, sum0, 1);
        sum0 += __shfl_xor_sync(0xFFFFFFFFu, sum0, 2);
        sum1 += __shfl_xor_sync(0xFFFFFFFFu, sum1, 1);
        sum1 += __shfl_xor_sync(0xFFFFFFFFu, sum1, 2);
        rL0 = rL0 * corr0 + sum0;
        rL1 = rL1 * corr1 + sum1;

#pragma unroll
        for (int nf = 0; nf < 16; nf++) {
            o[nf][0] *= corr0; o[nf][1] *= corr0;
            o[nf][2] *= corr1; o[nf][3] *= corr1;
        }

        // O += P V (P hi only, V hi only)
#pragma unroll
        for (int kk = 0; kk < 4; kk++) {
            const int vk = kk * 16;
#pragma unroll
            for (int vx = 0; vx < 8; vx++) {
                const int d0 = vx * 16;
                uint32_t vo = (uint32_t)(((vk + lrow) * LDQ + d0 + lcolh) * 2);
                uint32_t vh[4];
                LDSM_X4T(vh[0], vh[1], vh[2], vh[3], vh_b + vo);
                MMA16816(o[2 * vx], Ph[kk][0], Ph[kk][1], Ph[kk][2], Ph[kk][3], vh[0], vh[1]);
                MMA16816(o[2 * vx + 1], Ph[kk][0], Ph[kk][1], Ph[kk][2], Ph[kk][3], vh[2], vh[3]);
            }
        }
    }

    const float il0 = 1.f / rL0, il1 = 1.f / rL1;
#pragma unroll
    for (int nf = 0; nf < 16; nf++) {
        const int d = h * DH + nf * 8 + c0l;
        float f0 = o[nf][0] * il0, f1 = o[nf][1] * il0;
        float f2 = o[nf][2] * il1, f3 = o[nf][3] * il1;
        __half h0 = __float2half_rn(f0), h1 = __float2half_rn(f1);
        __half h2 = __float2half_rn(f2), h3 = __float2half_rn(f3);
        size_t o0 = (size_t)gq0 * HID_DIM + d;
        size_t o1 = (size_t)gq1 * HID_DIM + d;
        *(__half2*)(Oh + o0) = __halves2half2(h0, h1);
        *(__half2*)(Oh + o1) = __halves2half2(h2, h3);
        *(__half2*)(Ol + o0) = __halves2half2(
            __float2half_rn(f0 - __half2float(h0)),
            __float2half_rn(f1 - __half2float(h1)));
        *(__half2*)(Ol + o1) = __halves2half2(
            __float2half_rn(f2 - __half2float(h2)),
            __float2half_rn(f3 - __half2float(h3)));
    }
}

// ---------------------------------------------------------------------------
// Orchestration
// ---------------------------------------------------------------------------
extern "C" void kernel_launch(void* const* d_in, const int* in_sizes, int n_in,
                              void* d_out, int out_size)
{
    const float* hidden = (const float*)d_in[0];
    const float* wq = (const float*)d_in[2];
    const float* wk = (const float*)d_in[3];
    const float* wv = (const float*)d_in[4];
    const float* wo = (const float*)d_in[5];
    float* out = (float*)d_out;

    __half *hh, *hl, *qkvh, *qkvl, *ath, *atl, *wqkv, *wot;
    cudaGetSymbolAddress((void**)&hh, g_hid_hi);    cudaGetSymbolAddress((void**)&hl, g_hid_lo);
    cudaGetSymbolAddress((void**)&qkvh, g_qkv_hi);  cudaGetSymbolAddress((void**)&qkvl, g_qkv_lo);
    cudaGetSymbolAddress((void**)&ath, g_at_hi);    cudaGetSymbolAddress((void**)&atl, g_at_lo);
    cudaGetSymbolAddress((void**)&wqkv, g_wqkvT);   cudaGetSymbolAddress((void**)&wot, g_woT);

    cudaFuncSetAttribute(attn_mma_kernel, cudaFuncAttributeMaxDynamicSharedMemorySize, ATT_SMEM);
    cudaFuncSetAttribute(gemm_fp16x2_kernel, cudaFuncAttributeMaxDynamicSharedMemorySize, GEMM_SMEM);

    conv_hilo_kernel<<<(S_LEN * HID_DIM) / 1024, 256>>>(hidden, hh, hl, S_LEN * HID_DIM);
    dim3 tb(32, 8);
    conv_t_all_kernel<<<dim3(HID_DIM / 32, HID_DIM / 32, 4), tb>>>(
        wq, wk, wv, wo, wqkv, wot);

    gemm_fp16x2_kernel<<<dim3(QKVW / 128, S_LEN / 128), 256, GEMM_SMEM>>>(
        hh, hl, wqkv, nullptr, qkvh, qkvl, S_LEN, QKVW, HID_DIM);

    attn_mma_kernel<<<dim3(16, NH), 256, ATT_SMEM>>>(qkvh, qkvl, ath, atl);

    gemm_fp16x2_kernel<<<dim3(HID_DIM / 128, S_LEN / 128), 256, GEMM_SMEM>>>(
        ath, atl, wot, out, nullptr, nullptr, S_LEN, HID_DIM, HID_DIM);
}